// round 15
// baseline (speedup 1.0000x reference)
#include <cuda_runtime.h>
#include <cuda_bf16.h>
#include <stdint.h>
#include <math.h>

#define Nn 16384
#define Cc 256
#define KNN 10
#define NK (Nn*KNN)
#define NCAND 80   // 8 owner-threads * 10 per row

// ---------------- device global scratch ----------------
__device__ __nv_bfloat16 g_xb[(size_t)Nn*Cc];
__device__ float g_sq[Nn];
__device__ int   g_cand[(size_t)Nn*NCAND];
__device__ int   g_nbr[NK];
__device__ int   g_cnt[Nn];
__device__ int   g_ofs[Nn+1];
__device__ int   g_cur[Nn];
__device__ int   g_csc[NK];
__device__ float g_isd[Nn];
__device__ float g_ivd[Nn];
__device__ float g_hw[(size_t)Nn*Cc];
__device__ float g_h [(size_t)Nn*Cc];

// ---------------- fp32 -> bf16 conversion ----------------
__global__ void k_tobf(const float* __restrict__ x) {
    int i = blockIdx.x * 256 + threadIdx.x;
    float2 v = ((const float2*)x)[i];
    __nv_bfloat162 b;
    b.x = __float2bfloat16_rn(v.x);
    b.y = __float2bfloat16_rn(v.y);
    ((__nv_bfloat162*)g_xb)[i] = b;
}

// ---------------- row squared norms ----------------
__global__ void k_sq(const float* __restrict__ x) {
    int row  = blockIdx.x * 8 + (threadIdx.x >> 5);
    int lane = threadIdx.x & 31;
    const float* xr = x + (size_t)row * Cc;
    float s = 0.f;
    #pragma unroll
    for (int c = lane; c < Cc; c += 32) { float v = xr[c]; s += v * v; }
    #pragma unroll
    for (int o = 16; o; o >>= 1) s += __shfl_xor_sync(0xffffffffu, s, o);
    if (lane == 0) g_sq[row] = s;
}

__global__ void k_init() {
    int i = blockIdx.x * 256 + threadIdx.x;
    g_cnt[i] = 0;
    g_cur[i] = 0;
}

// ---------------- fused tensor-core kNN (coarse candidates) ----------------
// 256 CTAs x 64-row panels. B streamed in 256-col x 64-k chunks (pitch 144B),
// double-buffered. 8 warps = 4 row-bands x 2 col-halves; warp tile 16x128,
// acc[16][4]. Fully unrolled kc phases: all addresses are base + immediate.
// LDSM bytes per HMMA: 144 (vs 320 in the 16x64 version).

#define INS10(bv, bi, key, jj)                                   \
    if ((key) < bv[9]) {                                         \
        float cv = (key); int ci = (jj);                         \
        _Pragma("unroll")                                        \
        for (int u = 0; u < 10; u++) {                           \
            if (cv < bv[u]) {                                    \
                float tv = bv[u]; int ti = bi[u];                \
                bv[u] = cv; bi[u] = ci; cv = tv; ci = ti;        \
            }                                                    \
        }                                                        \
    }

#define CPASYNC16(dst_u32, src_ptr) \
    asm volatile("cp.async.cg.shared.global [%0], [%1], 16;" :: "r"(dst_u32), "l"(src_ptr))

#define KNN_SMEM 112640   // sA 36864 + sB 2*36864 + sSq 2048

// one 64-K chunk of MMAs over 128 cols; AK/BB compile-time byte offsets
#define MMA_KC(AK, BB)                                                         \
    _Pragma("unroll")                                                          \
    for (int ks = 0; ks < 4; ks++) {                                           \
        uint32_t a0, a1, a2, a3;                                               \
        asm volatile("ldmatrix.sync.aligned.m8n8.x4.shared.b16 {%0,%1,%2,%3}, [%4];" \
                     : "=r"(a0), "=r"(a1), "=r"(a2), "=r"(a3)                  \
                     : "r"(aAbase + (AK) + ks * 32));                          \
        _Pragma("unroll")                                                      \
        for (int p = 0; p < 8; p++) {                                          \
            uint32_t b0, b1, b2, b3;                                           \
            asm volatile("ldmatrix.sync.aligned.m8n8.x4.shared.b16 {%0,%1,%2,%3}, [%4];" \
                         : "=r"(b0), "=r"(b1), "=r"(b2), "=r"(b3)              \
                         : "r"(aBbase + (BB) + p * 2304 + ks * 32));           \
            asm volatile(                                                      \
                "mma.sync.aligned.m16n8k16.row.col.f32.bf16.bf16.f32 "         \
                "{%0,%1,%2,%3}, {%4,%5,%6,%7}, {%8,%9}, {%0,%1,%2,%3};"        \
                : "+f"(acc[2*p][0]), "+f"(acc[2*p][1]), "+f"(acc[2*p][2]), "+f"(acc[2*p][3]) \
                : "r"(a0), "r"(a1), "r"(a2), "r"(a3), "r"(b0), "r"(b2));       \
            asm volatile(                                                      \
                "mma.sync.aligned.m16n8k16.row.col.f32.bf16.bf16.f32 "         \
                "{%0,%1,%2,%3}, {%4,%5,%6,%7}, {%8,%9}, {%0,%1,%2,%3};"        \
                : "+f"(acc[2*p+1][0]), "+f"(acc[2*p+1][1]), "+f"(acc[2*p+1][2]), "+f"(acc[2*p+1][3]) \
                : "r"(a0), "r"(a1), "r"(a2), "r"(a3), "r"(b1), "r"(b3));       \
        }                                                                      \
    }

// prefetch one 256-col x 64-k B chunk: thread t owns column t (8 x 16B)
#define PREFETCH(NB, GOFF)                                                     \
    _Pragma("unroll")                                                          \
    for (int i = 0; i < 8; i++)                                                \
        CPASYNC16(dstb + (NB) + i * 16, gsrc + (GOFF) + i * 8);

#define WAITSYNC                                                               \
    asm volatile("cp.async.wait_group 0;");                                    \
    __syncthreads();

__global__ void __launch_bounds__(256, 2) k_knn() {
    extern __shared__ __align__(16) unsigned char dyn[];
    __nv_bfloat16* sA = (__nv_bfloat16*)dyn;                 // [4][64][72]   (kc, row, k)
    __nv_bfloat16* sB = (__nv_bfloat16*)(dyn + 36864);       // [2][256][72]  (buf, col, k)
    float*        sSq = (float*)(dyn + 110592);              // [2][256]

    int t = threadIdx.x;
    int lane = t & 31;
    int wid  = t >> 5;
    int band  = wid >> 1;          // rows band*16..+16
    int warpC = wid & 1;           // cols warpC*128..+128
    int r0 = blockIdx.x * 64;
    int lrow = lane & 15;
    int lkof = (lane >> 4) * 8;

    // ---- prologue: A panel (4 chunks) + B chunk (tile0,kc0) into buf 0
    #pragma unroll
    for (int i = 0; i < 8; i++) {
        int o = t * 8 + i;
        int kc = o >> 9, rem = o & 511;
        int row = rem >> 3, q = rem & 7;
        const __nv_bfloat16* g = &g_xb[(size_t)(r0 + row) * Cc + kc * 64 + q * 8];
        uint32_t d = (uint32_t)__cvta_generic_to_shared(&sA[(kc * 64 + row) * 72 + q * 8]);
        CPASYNC16(d, g);
    }
    #pragma unroll
    for (int i = 0; i < 8; i++) {
        const __nv_bfloat16* g = &g_xb[(size_t)t * Cc + i * 8];
        uint32_t d = (uint32_t)__cvta_generic_to_shared(&sB[t * 72 + i * 8]);
        CPASYNC16(d, g);
    }
    asm volatile("cp.async.commit_group;");

    // hoisted address bases (all later addresses are base + immediate)
    uint32_t aAbase = (uint32_t)__cvta_generic_to_shared(&sA[(band * 16 + lrow) * 72 + lkof]);
    uint32_t aBbase = (uint32_t)__cvta_generic_to_shared(&sB[(warpC * 128 + lrow) * 72 + lkof]);
    uint32_t dstb = (uint32_t)__cvta_generic_to_shared(&sB[t * 72]);
    const __nv_bfloat16* gsrc = g_xb + (size_t)t * Cc;   // (tile, kc0) base for col t

    float bvA[10], bvB[10];
    int   biA[10], biB[10];
    #pragma unroll
    for (int u = 0; u < 10; u++) { bvA[u] = 3.0e38f; biA[u] = -1; bvB[u] = 3.0e38f; biB[u] = -1; }

    float acc[16][4];

    for (int tile = 0; tile < 64; tile++) {
        // ---- kc 0 (compute buf 0; prefetch (tile,kc1) -> buf 1)
        WAITSYNC;
        sSq[(tile & 1) * 256 + t] = g_sq[tile * 256 + t];
        #pragma unroll
        for (int n = 0; n < 16; n++)
            #pragma unroll
            for (int e = 0; e < 4; e++) acc[n][e] = 0.f;
        PREFETCH(36864, 64);
        asm volatile("cp.async.commit_group;");
        MMA_KC(0, 0);

        // ---- kc 1 (compute buf 1; prefetch (tile,kc2) -> buf 0)
        WAITSYNC;
        PREFETCH(0, 128);
        asm volatile("cp.async.commit_group;");
        MMA_KC(9216, 36864);

        // ---- kc 2 (compute buf 0; prefetch (tile,kc3) -> buf 1)
        WAITSYNC;
        PREFETCH(36864, 192);
        asm volatile("cp.async.commit_group;");
        MMA_KC(18432, 0);

        // ---- kc 3 (compute buf 1; prefetch (tile+1,kc0) -> buf 0)
        WAITSYNC;
        if (tile < 63) { PREFETCH(0, 65536); }
        asm volatile("cp.async.commit_group;");
        MMA_KC(27648, 36864);
        gsrc += 65536;                        // advance to next tile's kc0 base

        // ---- selection epilogue for this tile: key = sq[j] - 2*dot
        {
            int c0 = tile * 256;
            const float* sq = &sSq[(tile & 1) * 256];
            #pragma unroll
            for (int nt = 0; nt < 16; nt++) {
                int cl = warpC * 128 + nt * 8 + 2 * (lane & 3);
                float sq0 = sq[cl], sq1 = sq[cl + 1];
                float k0 = fmaf(-2.f, acc[nt][0], sq0);
                float k1 = fmaf(-2.f, acc[nt][1], sq1);
                float k2 = fmaf(-2.f, acc[nt][2], sq0);
                float k3 = fmaf(-2.f, acc[nt][3], sq1);
                int j0 = c0 + cl;
                INS10(bvA, biA, k0, j0);
                INS10(bvA, biA, k1, j0 + 1);
                INS10(bvB, biB, k2, j0);
                INS10(bvB, biB, k3, j0 + 1);
            }
        }
    }

    // write candidates: 8 owner threads per row x 10 each
    int rowA = r0 + band * 16 + (lane >> 2);
    int rowB = rowA + 8;
    int slot = (warpC * 4 + (lane & 3)) * 10;
    #pragma unroll
    for (int u = 0; u < 10; u++) {
        g_cand[(size_t)rowA * NCAND + slot + u] = biA[u];
        g_cand[(size_t)rowB * NCAND + slot + u] = biB[u];
    }
}

// ---------------- exact fp32 rescore + top-10 (80 candidates) ----------------
__global__ void k_rescore(const float* __restrict__ x) {
    int row  = blockIdx.x * 8 + (threadIdx.x >> 5);
    int lane = threadIdx.x & 31;

    const float4* xp = (const float4*)(x + (size_t)row * Cc);
    float4 xr0 = xp[lane * 2];
    float4 xr1 = xp[lane * 2 + 1];
    float sqr = g_sq[row];

    float v[3];  int gi[3];
    #pragma unroll
    for (int q = 0; q < 3; q++) { v[q] = 3.0e38f; gi[q] = 0x7fffffff; }

    for (int c = 0; c < NCAND; c++) {
        int idx = g_cand[(size_t)row * NCAND + c];
        const float4* yp = (const float4*)(x + (size_t)idx * Cc);
        float4 ya = yp[lane * 2];
        float4 yb = yp[lane * 2 + 1];
        float s = xr0.x * ya.x;
        s = fmaf(xr0.y, ya.y, s); s = fmaf(xr0.z, ya.z, s); s = fmaf(xr0.w, ya.w, s);
        s = fmaf(xr1.x, yb.x, s); s = fmaf(xr1.y, yb.y, s);
        s = fmaf(xr1.z, yb.z, s); s = fmaf(xr1.w, yb.w, s);
        #pragma unroll
        for (int o = 16; o; o >>= 1) s += __shfl_xor_sync(0xffffffffu, s, o);
        float d2 = sqr + g_sq[idx] - 2.0f * s;
        if (idx == row) d2 = 3.0e38f;
        if (lane == (c & 31)) { v[c >> 5] = d2; gi[c >> 5] = idx; }
    }

    #pragma unroll
    for (int r = 0; r < KNN; r++) {
        float mv = v[0]; int mslot = 0;
        if (v[1] < mv || (v[1] == mv && gi[1] < gi[mslot])) { mv = v[1]; mslot = 1; }
        if (v[2] < mv || (v[2] == mv && gi[2] < gi[mslot])) { mv = v[2]; mslot = 2; }
        int mcol = gi[mslot];
        int mcode = lane * 4 + mslot;
        #pragma unroll
        for (int o = 16; o; o >>= 1) {
            float ov = __shfl_xor_sync(0xffffffffu, mv, o);
            int   oc = __shfl_xor_sync(0xffffffffu, mcol, o);
            int   od = __shfl_xor_sync(0xffffffffu, mcode, o);
            if (ov < mv || (ov == mv && oc < mcol)) { mv = ov; mcol = oc; mcode = od; }
        }
        if (lane == 0) g_nbr[row * KNN + r] = mcol;
        if (lane == (mcode >> 2)) v[mcode & 3] = 3.0e38f;
    }
}

// ---------------- degree / normalization / CSC ----------------
__global__ void k_deg() {
    int e = blockIdx.x * 256 + threadIdx.x;
    if (e < NK) atomicAdd(&g_cnt[g_nbr[e]], 1);
}

__global__ void k_invdeg() {
    int i = blockIdx.x * 256 + threadIdx.x;
    float d = (float)(g_cnt[i] + 1);
    g_isd[i] = rsqrtf(d);
    g_ivd[i] = 1.0f / d;
}

__global__ void k_scan() {
    __shared__ int part[256];
    int t = threadIdx.x;
    int base = t * 64;
    int s = 0;
    for (int u = 0; u < 64; u++) s += g_cnt[base + u];
    part[t] = s;
    __syncthreads();
    for (int o = 1; o < 256; o <<= 1) {
        int w = (t >= o) ? part[t - o] : 0;
        __syncthreads();
        part[t] += w;
        __syncthreads();
    }
    int run = part[t] - s;
    for (int u = 0; u < 64; u++) { g_ofs[base + u] = run; run += g_cnt[base + u]; }
    if (t == 255) g_ofs[Nn] = part[255];
}

__global__ void k_csc() {
    int e = blockIdx.x * 256 + threadIdx.x;
    if (e < NK) {
        int src = e / KNN;
        int dst = g_nbr[e];
        int p = atomicAdd(&g_cur[dst], 1);
        g_csc[g_ofs[dst] + p] = src;
    }
}

// ---------------- layer GEMM (round-6 proven version) ----------------
__global__ void __launch_bounds__(256) k_gemm(const float* __restrict__ Ax,
                                              const float* __restrict__ B, int use_h) {
    const float* A = use_h ? (const float*)g_h : Ax;
    __shared__ float As[32][129];
    __shared__ float Bs[32][129];
    int r0 = blockIdx.y * 128;
    int c0 = blockIdx.x * 128;
    int t = threadIdx.x;
    int ty = t >> 4, tx = t & 15;
    float acc[8][8] = {};

    for (int kk = 0; kk < Cc; kk += 32) {
        #pragma unroll
        for (int it = 0; it < 4; it++) {
            int q = t + 256 * it;
            int row = q >> 3, c4 = q & 7;
            float4 v = *(const float4*)(A + (size_t)(r0 + row) * Cc + kk + c4 * 4);
            As[c4*4+0][row] = v.x; As[c4*4+1][row] = v.y;
            As[c4*4+2][row] = v.z; As[c4*4+3][row] = v.w;
            int kb = q >> 5, cb = q & 31;
            float4 w = *(const float4*)(B + (size_t)(kk + kb) * Cc + c0 + cb * 4);
            Bs[kb][cb*4+0] = w.x; Bs[kb][cb*4+1] = w.y;
            Bs[kb][cb*4+2] = w.z; Bs[kb][cb*4+3] = w.w;
        }
        __syncthreads();
        #pragma unroll
        for (int k = 0; k < 32; k++) {
            float a[8], b[8];
            #pragma unroll
            for (int m = 0; m < 8; m++) a[m] = As[k][ty + 16*m];
            #pragma unroll
            for (int n = 0; n < 8; n++) b[n] = Bs[k][tx + 16*n];
            #pragma unroll
            for (int m = 0; m < 8; m++)
                #pragma unroll
                for (int n = 0; n < 8; n++) acc[m][n] += a[m] * b[n];
        }
        __syncthreads();
    }
    #pragma unroll
    for (int m = 0; m < 8; m++) {
        size_t r = (size_t)(r0 + ty + 16*m);
        #pragma unroll
        for (int n = 0; n < 8; n++)
            g_hw[r * Cc + c0 + tx + 16*n] = acc[m][n];
    }
}

// ---------------- GCN aggregation ----------------
__global__ void k_gather(const float* __restrict__ bias, float* __restrict__ outp,
                         int relu, int to_h) {
    int node = blockIdx.x * 8 + (threadIdx.x >> 5);
    int lane = threadIdx.x & 31;
    float4 a0 = make_float4(0.f, 0.f, 0.f, 0.f);
    float4 a1 = make_float4(0.f, 0.f, 0.f, 0.f);
    int s = g_ofs[node], e = g_ofs[node + 1];
    const float4* base = (const float4*)g_hw;

    for (int p = s; p < e; p++) {
        int i = g_csc[p];
        float w = g_isd[i];
        float4 p0 = base[(size_t)i * 64 + lane * 2];
        float4 p1 = base[(size_t)i * 64 + lane * 2 + 1];
        a0.x += w * p0.x; a0.y += w * p0.y; a0.z += w * p0.z; a0.w += w * p0.w;
        a1.x += w * p1.x; a1.y += w * p1.y; a1.z += w * p1.z; a1.w += w * p1.w;
    }

    float isdj = g_isd[node], ivd = g_ivd[node];
    float4 s0 = base[(size_t)node * 64 + lane * 2];
    float4 s1 = base[(size_t)node * 64 + lane * 2 + 1];
    const float4* b4 = (const float4*)bias;
    float4 b0 = b4[lane * 2], b1 = b4[lane * 2 + 1];

    float4 o0, o1;
    o0.x = a0.x * isdj + s0.x * ivd + b0.x;
    o0.y = a0.y * isdj + s0.y * ivd + b0.y;
    o0.z = a0.z * isdj + s0.z * ivd + b0.z;
    o0.w = a0.w * isdj + s0.w * ivd + b0.w;
    o1.x = a1.x * isdj + s1.x * ivd + b1.x;
    o1.y = a1.y * isdj + s1.y * ivd + b1.y;
    o1.z = a1.z * isdj + s1.z * ivd + b1.z;
    o1.w = a1.w * isdj + s1.w * ivd + b1.w;
    if (relu) {
        o0.x = fmaxf(o0.x, 0.f); o0.y = fmaxf(o0.y, 0.f);
        o0.z = fmaxf(o0.z, 0.f); o0.w = fmaxf(o0.w, 0.f);
        o1.x = fmaxf(o1.x, 0.f); o1.y = fmaxf(o1.y, 0.f);
        o1.z = fmaxf(o1.z, 0.f); o1.w = fmaxf(o1.w, 0.f);
    }
    float4* d4 = to_h ? (float4*)g_h : (float4*)outp;
    d4[(size_t)node * 64 + lane * 2]     = o0;
    d4[(size_t)node * 64 + lane * 2 + 1] = o1;
}

// ---------------- host driver ----------------
extern "C" void kernel_launch(void* const* d_in, const int* in_sizes, int n_in,
                              void* d_out, int out_size) {
    const float* x  = (const float*)d_in[0];
    const float* W1 = (const float*)d_in[1];
    const float* b1 = (const float*)d_in[2];
    const float* W2 = (const float*)d_in[3];
    const float* b2 = (const float*)d_in[4];
    const float* W3 = (const float*)d_in[5];
    const float* b3 = (const float*)d_in[6];
    float* out = (float*)d_out;

    cudaFuncSetAttribute(k_knn, cudaFuncAttributeMaxDynamicSharedMemorySize, KNN_SMEM);

    k_tobf<<<Nn * Cc / 512, 256>>>(x);
    k_sq  <<<Nn / 8, 256>>>(x);
    k_init<<<Nn / 256, 256>>>();
    k_knn <<<Nn / 64, 256, KNN_SMEM>>>();
    k_rescore<<<Nn / 8, 256>>>(x);
    k_deg   <<<NK / 256, 256>>>();
    k_invdeg<<<Nn / 256, 256>>>();
    k_scan  <<<1, 256>>>();
    k_csc   <<<NK / 256, 256>>>();

    k_gemm  <<<dim3(2, Nn / 128), 256>>>(x, W1, 0);
    k_gather<<<Nn / 8, 256>>>(b1, out, 1, 1);
    k_gemm  <<<dim3(2, Nn / 128), 256>>>(x, W2, 1);
    k_gather<<<Nn / 8, 256>>>(b2, out, 1, 1);
    k_gemm  <<<dim3(2, Nn / 128), 256>>>(x, W3, 1);
    k_gather<<<Nn / 8, 256>>>(b3, out, 0, 0);
}

// round 17
// speedup vs baseline: 1.2462x; 1.2462x over previous
#include <cuda_runtime.h>
#include <cuda_bf16.h>
#include <stdint.h>
#include <math.h>

#define Nn 16384
#define Cc 256
#define KNN 10
#define NK (Nn*KNN)
#define NCAND 80   // 8 owner-threads * 10 per row
#define NSEL 20    // exact-rescored subset (coarse top-20)

// ---------------- device global scratch ----------------
__device__ __nv_bfloat16 g_xb[(size_t)Nn*Cc];
__device__ float g_sq[Nn];
__device__ int   g_cand[(size_t)Nn*NCAND];
__device__ float g_ckey[(size_t)Nn*NCAND];
__device__ int   g_nbr[NK];
__device__ int   g_cnt[Nn];
__device__ int   g_ofs[Nn+1];
__device__ int   g_cur[Nn];
__device__ int   g_csc[NK];
__device__ float g_isd[Nn];
__device__ float g_ivd[Nn];
__device__ float g_hw[(size_t)Nn*Cc];
__device__ float g_h [(size_t)Nn*Cc];

// ---------------- fp32 -> bf16 conversion ----------------
__global__ void k_tobf(const float* __restrict__ x) {
    int i = blockIdx.x * 256 + threadIdx.x;
    float2 v = ((const float2*)x)[i];
    __nv_bfloat162 b;
    b.x = __float2bfloat16_rn(v.x);
    b.y = __float2bfloat16_rn(v.y);
    ((__nv_bfloat162*)g_xb)[i] = b;
}

// ---------------- row squared norms ----------------
__global__ void k_sq(const float* __restrict__ x) {
    int row  = blockIdx.x * 8 + (threadIdx.x >> 5);
    int lane = threadIdx.x & 31;
    const float* xr = x + (size_t)row * Cc;
    float s = 0.f;
    #pragma unroll
    for (int c = lane; c < Cc; c += 32) { float v = xr[c]; s += v * v; }
    #pragma unroll
    for (int o = 16; o; o >>= 1) s += __shfl_xor_sync(0xffffffffu, s, o);
    if (lane == 0) g_sq[row] = s;
}

__global__ void k_init() {
    int i = blockIdx.x * 256 + threadIdx.x;
    g_cnt[i] = 0;
    g_cur[i] = 0;
}

// ---------------- fused tensor-core kNN (coarse candidates) ----------------
// Round-14 kernel (proven 1064us): 256 CTAs x 64-row panels, B double-buffered
// 128x64 chunks, 8 warps = 4 row-bands x 2 col-halves, warp tile 16x64,
// fully unrolled kc phases (all addresses base + immediate).
// Epilogue additionally stores coarse keys for the rescore filter.

#define INS10(bv, bi, key, jj)                                   \
    if ((key) < bv[9]) {                                         \
        float cv = (key); int ci = (jj);                         \
        _Pragma("unroll")                                        \
        for (int u = 0; u < 10; u++) {                           \
            if (cv < bv[u]) {                                    \
                float tv = bv[u]; int ti = bi[u];                \
                bv[u] = cv; bi[u] = ci; cv = tv; ci = ti;        \
            }                                                    \
        }                                                        \
    }

#define CPASYNC16(dst_u32, src_ptr) \
    asm volatile("cp.async.cg.shared.global [%0], [%1], 16;" :: "r"(dst_u32), "l"(src_ptr))

#define KNN_SMEM 74752   // sA 36864 + sB 36864 + sSq 1024

#define MMA_KC(AK, BB)                                                         \
    _Pragma("unroll")                                                          \
    for (int ks = 0; ks < 4; ks++) {                                           \
        uint32_t a0, a1, a2, a3;                                               \
        asm volatile("ldmatrix.sync.aligned.m8n8.x4.shared.b16 {%0,%1,%2,%3}, [%4];" \
                     : "=r"(a0), "=r"(a1), "=r"(a2), "=r"(a3)                  \
                     : "r"(aAbase + (AK) + ks * 32));                          \
        _Pragma("unroll")                                                      \
        for (int p = 0; p < 4; p++) {                                          \
            uint32_t b0, b1, b2, b3;                                           \
            asm volatile("ldmatrix.sync.aligned.m8n8.x4.shared.b16 {%0,%1,%2,%3}, [%4];" \
                         : "=r"(b0), "=r"(b1), "=r"(b2), "=r"(b3)              \
                         : "r"(aBbase + (BB) + p * 2304 + ks * 32));           \
            asm volatile(                                                      \
                "mma.sync.aligned.m16n8k16.row.col.f32.bf16.bf16.f32 "         \
                "{%0,%1,%2,%3}, {%4,%5,%6,%7}, {%8,%9}, {%0,%1,%2,%3};"        \
                : "+f"(acc[2*p][0]), "+f"(acc[2*p][1]), "+f"(acc[2*p][2]), "+f"(acc[2*p][3]) \
                : "r"(a0), "r"(a1), "r"(a2), "r"(a3), "r"(b0), "r"(b2));       \
            asm volatile(                                                      \
                "mma.sync.aligned.m16n8k16.row.col.f32.bf16.bf16.f32 "         \
                "{%0,%1,%2,%3}, {%4,%5,%6,%7}, {%8,%9}, {%0,%1,%2,%3};"        \
                : "+f"(acc[2*p+1][0]), "+f"(acc[2*p+1][1]), "+f"(acc[2*p+1][2]), "+f"(acc[2*p+1][3]) \
                : "r"(a0), "r"(a1), "r"(a2), "r"(a3), "r"(b1), "r"(b3));       \
        }                                                                      \
    }

#define PREFETCH(NB, GOFF)                                                     \
    _Pragma("unroll")                                                          \
    for (int i = 0; i < 4; i++)                                                \
        CPASYNC16(dstb + (NB) + i * 16, gsrc + (GOFF) + i * 8);

#define WAITSYNC                                                               \
    asm volatile("cp.async.wait_group 0;");                                    \
    __syncthreads();

__global__ void __launch_bounds__(256, 2) k_knn() {
    extern __shared__ __align__(16) unsigned char dyn[];
    __nv_bfloat16* sA = (__nv_bfloat16*)dyn;                 // [4][64][72]  (kc, row, k)
    __nv_bfloat16* sB = (__nv_bfloat16*)(dyn + 36864);       // [2][128][72] (buf, col, k)
    float*        sSq = (float*)(dyn + 73728);               // [2][128]

    int t = threadIdx.x;
    int lane = t & 31;
    int wid  = t >> 5;
    int warpR = wid >> 1;          // rows warpR*16..+16
    int warpC = wid & 1;           // cols warpC*64..+64
    int r0 = blockIdx.x * 64;
    int lrow = lane & 15;
    int lkof = (lane >> 4) * 8;

    // ---- prologue: A panel (4 chunks) + B chunk (tile0,kc0) into buf 0
    #pragma unroll
    for (int i = 0; i < 8; i++) {
        int o = t * 8 + i;
        int kc = o >> 9, rem = o & 511;
        int row = rem >> 3, q = rem & 7;
        const __nv_bfloat16* g = &g_xb[(size_t)(r0 + row) * Cc + kc * 64 + q * 8];
        uint32_t d = (uint32_t)__cvta_generic_to_shared(&sA[(kc * 64 + row) * 72 + q * 8]);
        CPASYNC16(d, g);
    }
    {
        int row = t >> 1, q0 = (t & 1) * 4;
        #pragma unroll
        for (int i = 0; i < 4; i++) {
            const __nv_bfloat16* g = &g_xb[(size_t)row * Cc + (q0 + i) * 8];
            uint32_t d = (uint32_t)__cvta_generic_to_shared(&sB[row * 72 + (q0 + i) * 8]);
            CPASYNC16(d, g);
        }
    }
    asm volatile("cp.async.commit_group;");

    uint32_t aAbase = (uint32_t)__cvta_generic_to_shared(&sA[(warpR * 16 + lrow) * 72 + lkof]);
    uint32_t aBbase = (uint32_t)__cvta_generic_to_shared(&sB[(warpC * 64 + lrow) * 72 + lkof]);
    int pr_row = t >> 1, pr_q = (t & 1) * 4;
    uint32_t dstb = (uint32_t)__cvta_generic_to_shared(&sB[pr_row * 72 + pr_q * 8]);
    const __nv_bfloat16* gsrc = g_xb + (size_t)pr_row * Cc + pr_q * 8;  // (tile, kc0) base

    float bvA[10], bvB[10];
    int   biA[10], biB[10];
    #pragma unroll
    for (int u = 0; u < 10; u++) { bvA[u] = 3.0e38f; biA[u] = -1; bvB[u] = 3.0e38f; biB[u] = -1; }

    float acc[8][4];

    for (int tile = 0; tile < 128; tile++) {
        // ---- kc 0 (compute buf 0; prefetch (tile,kc1) -> buf 1)
        WAITSYNC;
        if (t < 128) sSq[(tile & 1) * 128 + t] = g_sq[tile * 128 + t];
        #pragma unroll
        for (int n = 0; n < 8; n++)
            #pragma unroll
            for (int e = 0; e < 4; e++) acc[n][e] = 0.f;
        PREFETCH(18432, 64);
        asm volatile("cp.async.commit_group;");
        MMA_KC(0, 0);

        // ---- kc 1 (compute buf 1; prefetch (tile,kc2) -> buf 0)
        WAITSYNC;
        PREFETCH(0, 128);
        asm volatile("cp.async.commit_group;");
        MMA_KC(9216, 18432);

        // ---- kc 2 (compute buf 0; prefetch (tile,kc3) -> buf 1)
        WAITSYNC;
        PREFETCH(18432, 192);
        asm volatile("cp.async.commit_group;");
        MMA_KC(18432, 0);

        // ---- kc 3 (compute buf 1; prefetch (tile+1,kc0) -> buf 0)
        WAITSYNC;
        if (tile < 127) { PREFETCH(0, 32768); }
        asm volatile("cp.async.commit_group;");
        MMA_KC(27648, 18432);
        gsrc += 32768;                        // advance to next tile's kc0 base

        // ---- selection epilogue for this tile: key = sq[j] - 2*dot
        {
            int c0 = tile * 128;
            const float* sq = &sSq[(tile & 1) * 128];
            #pragma unroll
            for (int nt = 0; nt < 8; nt++) {
                int cl = warpC * 64 + nt * 8 + 2 * (lane & 3);
                float sq0 = sq[cl], sq1 = sq[cl + 1];
                float k0 = fmaf(-2.f, acc[nt][0], sq0);
                float k1 = fmaf(-2.f, acc[nt][1], sq1);
                float k2 = fmaf(-2.f, acc[nt][2], sq0);
                float k3 = fmaf(-2.f, acc[nt][3], sq1);
                int j0 = c0 + cl;
                INS10(bvA, biA, k0, j0);
                INS10(bvA, biA, k1, j0 + 1);
                INS10(bvB, biB, k2, j0);
                INS10(bvB, biB, k3, j0 + 1);
            }
        }
    }

    // write candidates + coarse keys: 8 owner threads per row x 10 each
    int rowA = r0 + warpR * 16 + (lane >> 2);
    int rowB = rowA + 8;
    int slot = (warpC * 4 + (lane & 3)) * 10;
    #pragma unroll
    for (int u = 0; u < 10; u++) {
        g_cand[(size_t)rowA * NCAND + slot + u] = biA[u];
        g_cand[(size_t)rowB * NCAND + slot + u] = biB[u];
        g_ckey[(size_t)rowA * NCAND + slot + u] = bvA[u];
        g_ckey[(size_t)rowB * NCAND + slot + u] = bvB[u];
    }
}

// ---------------- rescore: coarse top-NSEL filter, exact fp32 on NSEL, top-10 ----------------
__global__ void k_rescore(const float* __restrict__ x) {
    int row  = blockIdx.x * 8 + (threadIdx.x >> 5);
    int lane = threadIdx.x & 31;

    // load 80 coarse (key, idx) pairs; exclude self
    float v[3];  int gi[3];
    #pragma unroll
    for (int q = 0; q < 3; q++) {
        int c = lane + 32 * q;
        if (c < NCAND) {
            int idx = g_cand[(size_t)row * NCAND + c];
            float k = g_ckey[(size_t)row * NCAND + c];
            if (idx == row || idx < 0) k = 3.0e38f;
            v[q] = k; gi[q] = (idx < 0) ? 0x7fffffff : idx;
        } else { v[q] = 3.0e38f; gi[q] = 0x7fffffff; }
    }

    // coarse top-NSEL by key (winner r parked on lane r)
    int mysel = 0x7fffffff;
    #pragma unroll
    for (int r = 0; r < NSEL; r++) {
        float mv = v[0]; int mslot = 0;
        if (v[1] < mv || (v[1] == mv && gi[1] < gi[mslot])) { mv = v[1]; mslot = 1; }
        if (v[2] < mv || (v[2] == mv && gi[2] < gi[mslot])) { mv = v[2]; mslot = 2; }
        int mcol = gi[mslot];
        int mcode = lane * 4 + mslot;
        #pragma unroll
        for (int o = 16; o; o >>= 1) {
            float ov = __shfl_xor_sync(0xffffffffu, mv, o);
            int   oc = __shfl_xor_sync(0xffffffffu, mcol, o);
            int   od = __shfl_xor_sync(0xffffffffu, mcode, o);
            if (ov < mv || (ov == mv && oc < mcol)) { mv = ov; mcol = oc; mcode = od; }
        }
        if (lane == r) mysel = mcol;
        if (lane == (mcode >> 2)) v[mcode & 3] = 3.0e38f;
    }

    // exact fp32 d2 for the NSEL selected candidates
    const float4* xp = (const float4*)(x + (size_t)row * Cc);
    float4 xr0 = xp[lane * 2];
    float4 xr1 = xp[lane * 2 + 1];
    float sqr = g_sq[row];

    float ev = 3.0e38f; int eidx = 0x7fffffff;
    #pragma unroll
    for (int c = 0; c < NSEL; c++) {
        int idx = __shfl_sync(0xffffffffu, mysel, c);
        const float4* yp = (const float4*)(x + (size_t)idx * Cc);
        float4 ya = yp[lane * 2];
        float4 yb = yp[lane * 2 + 1];
        float s = xr0.x * ya.x;
        s = fmaf(xr0.y, ya.y, s); s = fmaf(xr0.z, ya.z, s); s = fmaf(xr0.w, ya.w, s);
        s = fmaf(xr1.x, yb.x, s); s = fmaf(xr1.y, yb.y, s);
        s = fmaf(xr1.z, yb.z, s); s = fmaf(xr1.w, yb.w, s);
        #pragma unroll
        for (int o = 16; o; o >>= 1) s += __shfl_xor_sync(0xffffffffu, s, o);
        float d2 = sqr + g_sq[idx] - 2.0f * s;
        if (lane == c) { ev = d2; eidx = idx; }
    }

    // final exact top-10 (one candidate per lane 0..NSEL-1)
    #pragma unroll
    for (int r = 0; r < KNN; r++) {
        float mv = ev; int mcol = eidx; int ml = lane;
        #pragma unroll
        for (int o = 16; o; o >>= 1) {
            float ov = __shfl_xor_sync(0xffffffffu, mv, o);
            int   oc = __shfl_xor_sync(0xffffffffu, mcol, o);
            int   ol = __shfl_xor_sync(0xffffffffu, ml, o);
            if (ov < mv || (ov == mv && oc < mcol)) { mv = ov; mcol = oc; ml = ol; }
        }
        if (lane == 0) g_nbr[row * KNN + r] = mcol;
        if (lane == ml) ev = 3.0e38f;
    }
}

// ---------------- degree / normalization / CSC ----------------
__global__ void k_deg() {
    int e = blockIdx.x * 256 + threadIdx.x;
    if (e < NK) atomicAdd(&g_cnt[g_nbr[e]], 1);
}

__global__ void k_invdeg() {
    int i = blockIdx.x * 256 + threadIdx.x;
    float d = (float)(g_cnt[i] + 1);
    g_isd[i] = rsqrtf(d);
    g_ivd[i] = 1.0f / d;
}

__global__ void k_scan() {
    __shared__ int part[256];
    int t = threadIdx.x;
    int base = t * 64;
    int s = 0;
    for (int u = 0; u < 64; u++) s += g_cnt[base + u];
    part[t] = s;
    __syncthreads();
    for (int o = 1; o < 256; o <<= 1) {
        int w = (t >= o) ? part[t - o] : 0;
        __syncthreads();
        part[t] += w;
        __syncthreads();
    }
    int run = part[t] - s;
    for (int u = 0; u < 64; u++) { g_ofs[base + u] = run; run += g_cnt[base + u]; }
    if (t == 255) g_ofs[Nn] = part[255];
}

__global__ void k_csc() {
    int e = blockIdx.x * 256 + threadIdx.x;
    if (e < NK) {
        int src = e / KNN;
        int dst = g_nbr[e];
        int p = atomicAdd(&g_cur[dst], 1);
        g_csc[g_ofs[dst] + p] = src;
    }
}

// ---------------- layer GEMM (round-6 proven version) ----------------
__global__ void __launch_bounds__(256) k_gemm(const float* __restrict__ Ax,
                                              const float* __restrict__ B, int use_h) {
    const float* A = use_h ? (const float*)g_h : Ax;
    __shared__ float As[32][129];
    __shared__ float Bs[32][129];
    int r0 = blockIdx.y * 128;
    int c0 = blockIdx.x * 128;
    int t = threadIdx.x;
    int ty = t >> 4, tx = t & 15;
    float acc[8][8] = {};

    for (int kk = 0; kk < Cc; kk += 32) {
        #pragma unroll
        for (int it = 0; it < 4; it++) {
            int q = t + 256 * it;
            int row = q >> 3, c4 = q & 7;
            float4 v = *(const float4*)(A + (size_t)(r0 + row) * Cc + kk + c4 * 4);
            As[c4*4+0][row] = v.x; As[c4*4+1][row] = v.y;
            As[c4*4+2][row] = v.z; As[c4*4+3][row] = v.w;
            int kb = q >> 5, cb = q & 31;
            float4 w = *(const float4*)(B + (size_t)(kk + kb) * Cc + c0 + cb * 4);
            Bs[kb][cb*4+0] = w.x; Bs[kb][cb*4+1] = w.y;
            Bs[kb][cb*4+2] = w.z; Bs[kb][cb*4+3] = w.w;
        }
        __syncthreads();
        #pragma unroll
        for (int k = 0; k < 32; k++) {
            float a[8], b[8];
            #pragma unroll
            for (int m = 0; m < 8; m++) a[m] = As[k][ty + 16*m];
            #pragma unroll
            for (int n = 0; n < 8; n++) b[n] = Bs[k][tx + 16*n];
            #pragma unroll
            for (int m = 0; m < 8; m++)
                #pragma unroll
                for (int n = 0; n < 8; n++) acc[m][n] += a[m] * b[n];
        }
        __syncthreads();
    }
    #pragma unroll
    for (int m = 0; m < 8; m++) {
        size_t r = (size_t)(r0 + ty + 16*m);
        #pragma unroll
        for (int n = 0; n < 8; n++)
            g_hw[r * Cc + c0 + tx + 16*n] = acc[m][n];
    }
}

// ---------------- GCN aggregation ----------------
__global__ void k_gather(const float* __restrict__ bias, float* __restrict__ outp,
                         int relu, int to_h) {
    int node = blockIdx.x * 8 + (threadIdx.x >> 5);
    int lane = threadIdx.x & 31;
    float4 a0 = make_float4(0.f, 0.f, 0.f, 0.f);
    float4 a1 = make_float4(0.f, 0.f, 0.f, 0.f);
    int s = g_ofs[node], e = g_ofs[node + 1];
    const float4* base = (const float4*)g_hw;

    for (int p = s; p < e; p++) {
        int i = g_csc[p];
        float w = g_isd[i];
        float4 p0 = base[(size_t)i * 64 + lane * 2];
        float4 p1 = base[(size_t)i * 64 + lane * 2 + 1];
        a0.x += w * p0.x; a0.y += w * p0.y; a0.z += w * p0.z; a0.w += w * p0.w;
        a1.x += w * p1.x; a1.y += w * p1.y; a1.z += w * p1.z; a1.w += w * p1.w;
    }

    float isdj = g_isd[node], ivd = g_ivd[node];
    float4 s0 = base[(size_t)node * 64 + lane * 2];
    float4 s1 = base[(size_t)node * 64 + lane * 2 + 1];
    const float4* b4 = (const float4*)bias;
    float4 b0 = b4[lane * 2], b1 = b4[lane * 2 + 1];

    float4 o0, o1;
    o0.x = a0.x * isdj + s0.x * ivd + b0.x;
    o0.y = a0.y * isdj + s0.y * ivd + b0.y;
    o0.z = a0.z * isdj + s0.z * ivd + b0.z;
    o0.w = a0.w * isdj + s0.w * ivd + b0.w;
    o1.x = a1.x * isdj + s1.x * ivd + b1.x;
    o1.y = a1.y * isdj + s1.y * ivd + b1.y;
    o1.z = a1.z * isdj + s1.z * ivd + b1.z;
    o1.w = a1.w * isdj + s1.w * ivd + b1.w;
    if (relu) {
        o0.x = fmaxf(o0.x, 0.f); o0.y = fmaxf(o0.y, 0.f);
        o0.z = fmaxf(o0.z, 0.f); o0.w = fmaxf(o0.w, 0.f);
        o1.x = fmaxf(o1.x, 0.f); o1.y = fmaxf(o1.y, 0.f);
        o1.z = fmaxf(o1.z, 0.f); o1.w = fmaxf(o1.w, 0.f);
    }
    float4* d4 = to_h ? (float4*)g_h : (float4*)outp;
    d4[(size_t)node * 64 + lane * 2]     = o0;
    d4[(size_t)node * 64 + lane * 2 + 1] = o1;
}

// ---------------- host driver ----------------
extern "C" void kernel_launch(void* const* d_in, const int* in_sizes, int n_in,
                              void* d_out, int out_size) {
    const float* x  = (const float*)d_in[0];
    const float* W1 = (const float*)d_in[1];
    const float* b1 = (const float*)d_in[2];
    const float* W2 = (const float*)d_in[3];
    const float* b2 = (const float*)d_in[4];
    const float* W3 = (const float*)d_in[5];
    const float* b3 = (const float*)d_in[6];
    float* out = (float*)d_out;

    cudaFuncSetAttribute(k_knn, cudaFuncAttributeMaxDynamicSharedMemorySize, KNN_SMEM);

    k_tobf<<<Nn * Cc / 512, 256>>>(x);
    k_sq  <<<Nn / 8, 256>>>(x);
    k_init<<<Nn / 256, 256>>>();
    k_knn <<<Nn / 64, 256, KNN_SMEM>>>();
    k_rescore<<<Nn / 8, 256>>>(x);
    k_deg   <<<NK / 256, 256>>>();
    k_invdeg<<<Nn / 256, 256>>>();
    k_scan  <<<1, 256>>>();
    k_csc   <<<NK / 256, 256>>>();

    k_gemm  <<<dim3(2, Nn / 128), 256>>>(x, W1, 0);
    k_gather<<<Nn / 8, 256>>>(b1, out, 1, 1);
    k_gemm  <<<dim3(2, Nn / 128), 256>>>(x, W2, 1);
    k_gather<<<Nn / 8, 256>>>(b2, out, 1, 1);
    k_gemm  <<<dim3(2, Nn / 128), 256>>>(x, W3, 1);
    k_gather<<<Nn / 8, 256>>>(b3, out, 0, 0);
}